// round 16
// baseline (speedup 1.0000x reference)
#include <cuda_runtime.h>
#include <cuda_bf16.h>
#include <math.h>
#include <stdint.h>

// ---------------- problem constants ----------------
#define HIDC  256
#define NHEAD 8
#define NN1   60
#define NN2   240
#define NN3   300
#define LLAB  600
#define DHH   32
#define BBAT  32
#define SSEQ  512
#define DBERT 768
#define NSPLIT 64
#define LSPLIT 300           // label split: l<300 <=> z<32
#define ZSPLIT 32
#define KOUT  (LLAB * HIDC)  // 153600
#define KSLC  (KOUT / NSPLIT) // 2400

#define ATTN_SMEM (32 * 601 * 4)

// ---------------- device scratch ----------------
__device__ float g_text_enc[BBAT * SSEQ * HIDC];
__device__ float g_le      [LLAB * HIDC];
__device__ float g_Kb      [LLAB * HIDC];
__device__ float g_PAQ     [LLAB * HIDC];
__device__ float g_PMV     [LLAB * HIDC];
__device__ float g_M       [LLAB * HIDC];
__device__ float g_aw      [BBAT * LLAB * SSEQ];
__device__ float g_part    [NSPLIT * BBAT * LLAB];
__device__ float g_WQe     [3 * HIDC * HIDC];
__device__ float g_WVe     [3 * HIDC * HIDC];
__device__ __nv_bfloat16 g_feat_bf[BBAT * LLAB * HIDC];
__device__ __nv_bfloat16 g_Wout_bf[(size_t)LLAB * KOUT];   // 184 MB

static inline int cdiv(int a, int b) { return (a + b - 1) / b; }

// =====================================================================
// helpers
// =====================================================================
__device__ __forceinline__ uint32_t f2tf(float x) {
    uint32_t r;
    asm("cvt.rna.tf32.f32 %0, %1;" : "=r"(r) : "f"(x));
    return r;
}

__device__ __forceinline__ uint32_t bf2x_to_u32(__nv_bfloat162 v) {
    uint32_t r;
    memcpy(&r, &v, 4);
    return r;
}

__device__ __forceinline__ void mma_tf32(float* c, const uint32_t* a, const uint32_t* b) {
    asm("mma.sync.aligned.m16n8k8.row.col.f32.tf32.tf32.f32 "
        "{%0,%1,%2,%3}, {%4,%5,%6,%7}, {%8,%9}, {%0,%1,%2,%3};"
        : "+f"(c[0]), "+f"(c[1]), "+f"(c[2]), "+f"(c[3])
        : "r"(a[0]), "r"(a[1]), "r"(a[2]), "r"(a[3]), "r"(b[0]), "r"(b[1]));
}

__device__ __forceinline__ void mma_bf16(float* c, const uint32_t* a, const uint32_t* b) {
    asm("mma.sync.aligned.m16n8k16.row.col.f32.bf16.bf16.f32 "
        "{%0,%1,%2,%3}, {%4,%5,%6,%7}, {%8,%9}, {%0,%1,%2,%3};"
        : "+f"(c[0]), "+f"(c[1]), "+f"(c[2]), "+f"(c[3])
        : "r"(a[0]), "r"(a[1]), "r"(a[2]), "r"(a[3]), "r"(b[0]), "r"(b[1]));
}

__device__ __forceinline__ void cpa16(void* s, const void* g, bool v) {
    uint32_t sa = (uint32_t)__cvta_generic_to_shared(s);
    int sz = v ? 16 : 0;
    asm volatile("cp.async.cg.shared.global [%0], [%1], 16, %2;" :: "r"(sa), "l"(g), "r"(sz));
}
__device__ __forceinline__ void cp_commit() { asm volatile("cp.async.commit_group;"); }
__device__ __forceinline__ void cp_wait1()  { asm volatile("cp.async.wait_group 1;"); }
__device__ __forceinline__ void cp_wait0()  { asm volatile("cp.async.wait_group 0;"); }

// =====================================================================
// 2-stage cp.async pipelined tf32 GEMM (device body)
// MODE 0: Y = acc (+bias[n]) ; MODE 1: Y = tanh(acc+bias) ; MODE 2: Y = tanh(acc)+res
// OUTBF16: write output as bf16 (MODE 0 only)
// =====================================================================
template<int BM, int BN, int BK, int WM, int WN, int MODE, bool TRANS_W, bool OUTBF16 = false>
__device__ __forceinline__ void tgemm_dev(
    const float* __restrict__ X, const float* __restrict__ W,
    const float* __restrict__ bias, const float* __restrict__ res,
    float* __restrict__ Y,
    int M, int N, int K, int ldx, int ldw, int ldy)
{
    constexpr int NWARP = (BM / WM) * (BN / WN);
    constexpr int NTHR  = NWARP * 32;
    constexpr int LDA   = BK + 4;
    constexpr int LDBN  = BK + 4;
    constexpr int LDBT  = BN + 8;
    constexpr int MI = WM / 16, NI = WN / 8;

    __shared__ float As[2][BM * LDA];
    __shared__ float Bs[2][TRANS_W ? (BK * LDBT) : (BN * LDBN)];

    const int m0 = blockIdx.y * BM, n0 = blockIdx.x * BN;
    const int tid  = threadIdx.x;
    const int lane = tid & 31, wid = tid >> 5;
    const int wN = wid % (BN / WN), wM = wid / (BN / WN);
    const int g = lane >> 2, tg = lane & 3;

    float acc[MI][NI][4];
    #pragma unroll
    for (int i = 0; i < MI; i++)
        #pragma unroll
        for (int j = 0; j < NI; j++)
            #pragma unroll
            for (int r = 0; r < 4; r++) acc[i][j][r] = 0.f;

    const int T = K / BK;

    auto load_tile = [&](int t, int st) {
        int k0 = t * BK;
        #pragma unroll
        for (int c = tid; c < BM * (BK / 4); c += NTHR) {
            int row = c >> 2, kq = (c & 3) * 4;
            bool v = (m0 + row) < M;
            int gr = v ? (m0 + row) : 0;
            cpa16(&As[st][row * LDA + kq], X + (long)gr * ldx + k0 + kq, v);
        }
        if (!TRANS_W) {
            #pragma unroll
            for (int c = tid; c < BN * (BK / 4); c += NTHR) {
                int row = c >> 2, kq = (c & 3) * 4;
                bool v = (n0 + row) < N;
                int gr = v ? (n0 + row) : 0;
                cpa16(&Bs[st][row * LDBN + kq], W + (long)gr * ldw + k0 + kq, v);
            }
        } else {
            #pragma unroll
            for (int c = tid; c < BK * (BN / 4); c += NTHR) {
                int k = c / (BN / 4), nq = (c % (BN / 4)) * 4;
                bool v = (n0 + nq) < N;
                int gc = v ? (n0 + nq) : 0;
                cpa16(&Bs[st][k * LDBT + nq], W + (long)(k0 + k) * ldw + gc, v);
            }
        }
    };

    load_tile(0, 0);
    cp_commit();

    for (int t = 0; t < T; t++) {
        int cur = t & 1;
        if (t + 1 < T) {
            load_tile(t + 1, cur ^ 1);
            cp_commit();
            cp_wait1();
        } else {
            cp_wait0();
        }
        __syncthreads();

        #pragma unroll
        for (int kk = 0; kk < BK; kk += 8) {
            uint32_t a[MI][4], b[NI][2];
            #pragma unroll
            for (int mi = 0; mi < MI; mi++) {
                int mr = wM * WM + mi * 16;
                a[mi][0] = f2tf(As[cur][(mr + g)     * LDA + kk + tg]);
                a[mi][1] = f2tf(As[cur][(mr + g + 8) * LDA + kk + tg]);
                a[mi][2] = f2tf(As[cur][(mr + g)     * LDA + kk + tg + 4]);
                a[mi][3] = f2tf(As[cur][(mr + g + 8) * LDA + kk + tg + 4]);
            }
            #pragma unroll
            for (int ni = 0; ni < NI; ni++) {
                int nc = wN * WN + ni * 8;
                if (!TRANS_W) {
                    b[ni][0] = f2tf(Bs[cur][(nc + g) * LDBN + kk + tg]);
                    b[ni][1] = f2tf(Bs[cur][(nc + g) * LDBN + kk + tg + 4]);
                } else {
                    b[ni][0] = f2tf(Bs[cur][(kk + tg)     * LDBT + nc + g]);
                    b[ni][1] = f2tf(Bs[cur][(kk + tg + 4) * LDBT + nc + g]);
                }
            }
            #pragma unroll
            for (int mi = 0; mi < MI; mi++)
                #pragma unroll
                for (int ni = 0; ni < NI; ni++)
                    mma_tf32(acc[mi][ni], a[mi], b[ni]);
        }
        __syncthreads();
    }

    #pragma unroll
    for (int mi = 0; mi < MI; mi++) {
        #pragma unroll
        for (int ni = 0; ni < NI; ni++) {
            int mr = m0 + wM * WM + mi * 16 + g;
            int nc = n0 + wN * WN + ni * 8 + 2 * tg;
            #pragma unroll
            for (int r = 0; r < 4; r++) {
                int m = mr + (r >> 1) * 8;
                int n = nc + (r & 1);
                if (m >= M || n >= N) continue;
                float v = acc[mi][ni][r];
                if (MODE == 0)      { if (bias) v += bias[n]; }
                else if (MODE == 1) { v = tanhf(v + bias[n]); }
                else if (MODE == 2) { v = tanhf(v) + res[(long)m * ldy + n]; }
                if (OUTBF16) ((__nv_bfloat16*)Y)[(long)m * ldy + n] = __float2bfloat16(v);
                else         Y[(long)m * ldy + n] = v;
            }
        }
    }
}

template<int BM, int BN, int BK, int WM, int WN, int MODE, bool TRANS_W, bool OUTBF16 = false>
__global__ void __launch_bounds__((BM / WM) * (BN / WN) * 32)
tgemm_g(const float* __restrict__ Xg, const float* __restrict__ Wg,
        const float* __restrict__ bias, float* __restrict__ Yg,
        int M, int N, int K, int ldx, int ldw, int ldy,
        long bsx, long bsw, long bsy)
{
    int bz = blockIdx.z;
    float* Yp = OUTBF16 ? (float*)((__nv_bfloat16*)Yg + bz * bsy) : (Yg + bz * bsy);
    tgemm_dev<BM, BN, BK, WM, WN, MODE, TRANS_W, OUTBF16>(
        Xg + bz * bsx, Wg + bz * bsw, bias, nullptr, Yp,
        M, N, K, ldx, ldw, ldy);
}

// =====================================================================
// Wout fp32 -> bf16 conversion (grid-stride, 8 elems/thread/iter)
// =====================================================================
__global__ void wout_to_bf16(const float* __restrict__ W, __nv_bfloat16* __restrict__ Wb, long n)
{
    long stride = (long)gridDim.x * blockDim.x * 8;
    for (long i = ((long)blockIdx.x * blockDim.x + threadIdx.x) * 8; i < n; i += stride) {
        float4 v0 = *(const float4*)(W + i);
        float4 v1 = *(const float4*)(W + i + 4);
        uint4 o;
        o.x = bf2x_to_u32(__floats2bfloat162_rn(v0.x, v0.y));
        o.y = bf2x_to_u32(__floats2bfloat162_rn(v0.z, v0.w));
        o.z = bf2x_to_u32(__floats2bfloat162_rn(v1.x, v1.y));
        o.w = bf2x_to_u32(__floats2bfloat162_rn(v1.z, v1.w));
        *(uint4*)(Wb + i) = o;
    }
}

// =====================================================================
// bf16 final split-K GEMM: part[z][m][n] = sum_k A[m, zoff+k] * B[n, zoff+k]
// A = feat_bf [32 x 153600], B = Wout_bf [600 x 153600], K per slice = 2400.
// BM=32, BN=128, BK=32(k)=16(u32); 8 warps (2 M x 4 N), WM=16, WN=32.
// =====================================================================
__global__ void __launch_bounds__(256)
bgemm_final(const __nv_bfloat16* __restrict__ A, const __nv_bfloat16* __restrict__ B,
            float* __restrict__ part, int zbase)
{
    constexpr int BK2 = 16, LD2 = BK2 + 4;   // u32 columns per tile + pad
    __shared__ uint32_t As[2][32 * LD2];
    __shared__ uint32_t Bs[2][128 * LD2];

    const int z = zbase + blockIdx.z;
    const long zoff = (long)z * KSLC;
    const int n0 = blockIdx.x * 128;
    const int tid = threadIdx.x, lane = tid & 31, wid = tid >> 5;
    const int wN = wid & 3, wM = wid >> 2;
    const int g = lane >> 2, tg = lane & 3;

    float acc[4][4];
    #pragma unroll
    for (int i = 0; i < 4; i++)
        #pragma unroll
        for (int r = 0; r < 4; r++) acc[i][r] = 0.f;

    const int T = KSLC / 32;   // 75

    auto load_tile = [&](int t, int st) {
        long k0 = zoff + (long)t * 32;
        // A: 32 rows x 4 chunks of 16B
        if (tid < 128) {
            int row = tid >> 2, ch = tid & 3;
            cpa16(&As[st][row * LD2 + ch * 4], A + (long)row * KOUT + k0 + ch * 8, true);
        }
        // B: 128 rows x 4 chunks
        #pragma unroll
        for (int c = tid; c < 512; c += 256) {
            int row = c >> 2, ch = c & 3;
            bool v = (n0 + row) < LLAB;
            int gr = v ? (n0 + row) : 0;
            cpa16(&Bs[st][row * LD2 + ch * 4], B + (long)gr * KOUT + k0 + ch * 8, v);
        }
    };

    load_tile(0, 0);
    cp_commit();

    for (int t = 0; t < T; t++) {
        int cur = t & 1;
        if (t + 1 < T) {
            load_tile(t + 1, cur ^ 1);
            cp_commit();
            cp_wait1();
        } else {
            cp_wait0();
        }
        __syncthreads();

        #pragma unroll
        for (int kk2 = 0; kk2 < BK2; kk2 += 8) {
            uint32_t a[4], b[4][2];
            int mr = wM * 16;
            a[0] = As[cur][(mr + g)     * LD2 + kk2 + tg];
            a[1] = As[cur][(mr + g + 8) * LD2 + kk2 + tg];
            a[2] = As[cur][(mr + g)     * LD2 + kk2 + tg + 4];
            a[3] = As[cur][(mr + g + 8) * LD2 + kk2 + tg + 4];
            #pragma unroll
            for (int ni = 0; ni < 4; ni++) {
                int nc = wN * 32 + ni * 8;
                b[ni][0] = Bs[cur][(nc + g) * LD2 + kk2 + tg];
                b[ni][1] = Bs[cur][(nc + g) * LD2 + kk2 + tg + 4];
            }
            #pragma unroll
            for (int ni = 0; ni < 4; ni++)
                mma_bf16(acc[ni], a, b[ni]);
        }
        __syncthreads();
    }

    float* po = part + (long)z * (BBAT * LLAB);
    #pragma unroll
    for (int ni = 0; ni < 4; ni++) {
        #pragma unroll
        for (int r = 0; r < 4; r++) {
            int m = wM * 16 + g + (r >> 1) * 8;
            int n = n0 + wN * 32 + ni * 8 + 2 * tg + (r & 1);
            if (n < LLAB)
                po[m * LLAB + n] = acc[ni][r];
        }
    }
}

// =====================================================================
// Effective weights
// =====================================================================
__global__ void prep_eff(const float* __restrict__ WQ, const float* __restrict__ WV,
                         const float* __restrict__ PA, const float* __restrict__ PM,
                         float* __restrict__ WQe, float* __restrict__ WVe)
{
    int t = blockIdx.x >> 3, h = blockIdx.x & 7;
    const float* W = (blockIdx.y == 0 ? WQ : WV) + (long)t * HIDC * HIDC + (long)h * DHH * HIDC;
    const float* P = (blockIdx.y == 0 ? PA : PM);
    float* O = (blockIdx.y == 0 ? WQe : WVe) + (long)t * HIDC * HIDC + (long)h * DHH * HIDC;

    __shared__ float Ps[DHH][DHH];
    int tid = threadIdx.x;
    for (int i = tid; i < DHH * DHH; i += 256) Ps[i / DHH][i % DHH] = P[i];
    __syncthreads();

    int c = tid;
    float w[DHH];
    #pragma unroll
    for (int d = 0; d < DHH; d++) w[d] = W[(long)d * HIDC + c];
    #pragma unroll
    for (int e = 0; e < DHH; e++) {
        float s = 0.f;
        #pragma unroll
        for (int d = 0; d < DHH; d++) s += Ps[e][d] * w[d];
        O[(long)e * HIDC + c] = s;
    }
}

// =====================================================================
// Fused per-type projections: grid (4, 5, 9), 128 threads
// =====================================================================
__global__ void __launch_bounds__(128)
proj_fused(const float* __restrict__ le,
           const float* __restrict__ WK,
           const float* __restrict__ WQe,
           const float* __restrict__ WVe,
           float* __restrict__ Kb, float* __restrict__ PAQ,
           float* __restrict__ PMV)
{
    int z = blockIdx.z;
    int t = z % 3, which = z / 3;
    int s0 = (t == 0) ? 0 : (t == 1 ? NN1 : NN1 + NN2);
    int cnt = (t == 0) ? NN1 : (t == 1 ? NN2 : NN3);
    if ((int)blockIdx.y * 64 >= cnt) return;
    const float* W = (which == 0 ? WK : (which == 1 ? WQe : WVe)) + (long)t * HIDC * HIDC;
    float* Y = (which == 0 ? Kb : (which == 1 ? PAQ : PMV)) + (long)s0 * HIDC;
    tgemm_dev<64, 64, 16, 32, 32, 0, false>(
        le + (long)s0 * HIDC, W, nullptr, nullptr, Y,
        cnt, HIDC, HIDC, HIDC, HIDC, HIDC);
}

__global__ void __launch_bounds__(128)
wa_fused(const float* __restrict__ Mm, const float* __restrict__ WA,
         float* __restrict__ le)
{
    int t = blockIdx.z;
    int s0 = (t == 0) ? 0 : (t == 1 ? NN1 : NN1 + NN2);
    int cnt = (t == 0) ? NN1 : (t == 1 ? NN2 : NN3);
    if ((int)blockIdx.y * 64 >= cnt) return;
    tgemm_dev<64, 64, 16, 32, 32, 2, false>(
        Mm + (long)s0 * HIDC, WA + (long)t * HIDC * HIDC, nullptr,
        le + (long)s0 * HIDC, le + (long)s0 * HIDC,
        cnt, HIDC, HIDC, HIDC, HIDC, HIDC);
}

// =====================================================================
// Fused HGT attention
// =====================================================================
__global__ void __launch_bounds__(256)
attn_fused(const float* __restrict__ paq, const float* __restrict__ Kb,
           const float* __restrict__ pmv, const int* __restrict__ amask,
           float* __restrict__ Mout)
{
    extern __shared__ float Ss[];
    __shared__ float invs[32];
    const float scale = 0.17677669529663687f;

    const int qt = blockIdx.x, h = blockIdx.y;
    const int q0 = qt * 32, hd = h * DHH;
    const int tid = threadIdx.x, lane = tid & 31, wid = tid >> 5;

    {
        int gq = q0 + lane;
        int qc = (gq < LLAB) ? gq : (LLAB - 1);
        float qreg[DHH];
        #pragma unroll
        for (int d = 0; d < DHH; d++) qreg[d] = paq[(long)qc * HIDC + hd + d];

        int kend = wid * 75 + 75;
        for (int k = wid * 75; k < kend; k++) {
            float kv = Kb[(long)k * HIDC + hd + lane];
            float s = 0.f;
            #pragma unroll
            for (int d = 0; d < DHH; d++)
                s = fmaf(qreg[d], __shfl_sync(0xffffffffu, kv, d), s);
            Ss[lane * 601 + k] = s;
        }
    }
    __syncthreads();

    #pragma unroll
    for (int rr = 0; rr < 4; rr++) {
        int q = wid * 4 + rr;
        int gq = q0 + q;
        if (gq >= LLAB) continue;
        bool qb1 = (gq < NN1), qb3 = (gq >= NN1 + NN2);

        float mx = -INFINITY;
        for (int k = lane; k < LLAB; k += 32) {
            bool kb1 = (k < NN1), kb3 = (k >= NN1 + NN2);
            bool Z = (qb1 && kb3) || (qb3 && kb1);
            float mk = (amask[(long)gq * LLAB + k] == 0) ? -INFINITY : 0.f;
            float v = (Z ? 0.f : Ss[q * 601 + k] * scale) + mk;
            Ss[q * 601 + k] = v;
            mx = fmaxf(mx, v);
        }
        #pragma unroll
        for (int o = 16; o; o >>= 1) mx = fmaxf(mx, __shfl_xor_sync(0xffffffffu, mx, o));

        float sum = 0.f;
        for (int k = lane; k < LLAB; k += 32) {
            bool kb1 = (k < NN1), kb3 = (k >= NN1 + NN2);
            bool Z = (qb1 && kb3) || (qb3 && kb1);
            float e = expf(Ss[q * 601 + k] - mx);
            sum += e;
            Ss[q * 601 + k] = Z ? 0.f : e;
        }
        #pragma unroll
        for (int o = 16; o; o >>= 1) sum += __shfl_xor_sync(0xffffffffu, sum, o);
        if (lane == 0) invs[q] = 1.f / sum;
    }
    __syncthreads();

    {
        float acc0 = 0.f, acc1 = 0.f, acc2 = 0.f, acc3 = 0.f;
        const int qb = wid * 4;
        for (int k = 0; k < LLAB; k += 2) {
            float pv0 = pmv[(long)k * HIDC + hd + lane];
            float pv1 = pmv[(long)(k + 1) * HIDC + hd + lane];
            acc0 = fmaf(Ss[(qb + 0) * 601 + k], pv0, acc0);
            acc1 = fmaf(Ss[(qb + 1) * 601 + k], pv0, acc1);
            acc2 = fmaf(Ss[(qb + 2) * 601 + k], pv0, acc2);
            acc3 = fmaf(Ss[(qb + 3) * 601 + k], pv0, acc3);
            acc0 = fmaf(Ss[(qb + 0) * 601 + k + 1], pv1, acc0);
            acc1 = fmaf(Ss[(qb + 1) * 601 + k + 1], pv1, acc1);
            acc2 = fmaf(Ss[(qb + 2) * 601 + k + 1], pv1, acc2);
            acc3 = fmaf(Ss[(qb + 3) * 601 + k + 1], pv1, acc3);
        }
        float accs[4] = {acc0, acc1, acc2, acc3};
        #pragma unroll
        for (int rr = 0; rr < 4; rr++) {
            int gq = q0 + qb + rr;
            if (gq < LLAB)
                Mout[(long)gq * HIDC + hd + lane] = accs[rr] * invs[qb + rr];
        }
    }
}

// ---------------- pooling softmax over S with pad mask (l-range version) ----------------
__global__ void pool_softmax(float* __restrict__ aw, const int* __restrict__ tok, int l0)
{
    const int l = l0 + blockIdx.x, b = blockIdx.y;
    float* row = aw + ((long)b * LLAB + l) * SSEQ;
    const int* t = tok + (long)b * SSEQ;

    __shared__ float buf[SSEQ];
    __shared__ float red[33];
    const int tid = threadIdx.x;   // 256

    float mx = -INFINITY;
    for (int s = tid; s < SSEQ; s += 256) {
        int tv = t[s];
        bool bad = (tv == 0) || (tv == 101) || (tv == 102);
        float v = row[s] + (bad ? -INFINITY : 0.f);
        buf[s] = v;
        mx = fmaxf(mx, v);
    }
    for (int o = 16; o; o >>= 1) mx = fmaxf(mx, __shfl_xor_sync(0xffffffffu, mx, o));
    if ((tid & 31) == 0) red[tid >> 5] = mx;
    __syncthreads();
    if (tid < 32) {
        float v = (tid < 8) ? red[tid] : -INFINITY;
        for (int o = 16; o; o >>= 1) v = fmaxf(v, __shfl_xor_sync(0xffffffffu, v, o));
        if (tid == 0) red[32] = v;
    }
    __syncthreads();
    mx = red[32];
    __syncthreads();

    float sum = 0.f;
    for (int s = tid; s < SSEQ; s += 256) {
        float e = expf(buf[s] - mx);
        buf[s] = e;
        sum += e;
    }
    for (int o = 16; o; o >>= 1) sum += __shfl_xor_sync(0xffffffffu, sum, o);
    if ((tid & 31) == 0) red[tid >> 5] = sum;
    __syncthreads();
    if (tid < 32) {
        float v = (tid < 8) ? red[tid] : 0.f;
        for (int o = 16; o; o >>= 1) v += __shfl_xor_sync(0xffffffffu, v, o);
        if (tid == 0) red[32] = v;
    }
    __syncthreads();
    float inv = 1.f / red[32];

    for (int s = tid; s < SSEQ; s += 256) row[s] = buf[s] * inv;
}

// ---------------- final split-K reduce + sigmoid ----------------
__global__ void final_reduce(const float* __restrict__ part,
                             const float* __restrict__ bout,
                             float* __restrict__ out)
{
    int i = blockIdx.x * blockDim.x + threadIdx.x;
    if (i >= BBAT * LLAB) return;
    int l = i % LLAB;
    float s = bout[l];
    #pragma unroll
    for (int z = 0; z < NSPLIT; z++) s += part[z * (BBAT * LLAB) + i];
    out[i] = 1.f / (1.f + expf(-s));
}

// ---------------- streams for overlap (created at static init) ----------------
struct HgtStreams {
    cudaStream_t s_te = nullptr, s_w = nullptr;
    cudaEvent_t ev_fork = nullptr, ev_te = nullptr, ev_le = nullptr,
                ev_c1 = nullptr, ev_wout = nullptr;
    HgtStreams() {
        bool ok = true;
        ok = ok && cudaStreamCreateWithFlags(&s_te, cudaStreamNonBlocking) == cudaSuccess;
        ok = ok && cudaStreamCreateWithFlags(&s_w, cudaStreamNonBlocking) == cudaSuccess;
        ok = ok && cudaEventCreateWithFlags(&ev_fork, cudaEventDisableTiming) == cudaSuccess;
        ok = ok && cudaEventCreateWithFlags(&ev_te, cudaEventDisableTiming) == cudaSuccess;
        ok = ok && cudaEventCreateWithFlags(&ev_le, cudaEventDisableTiming) == cudaSuccess;
        ok = ok && cudaEventCreateWithFlags(&ev_c1, cudaEventDisableTiming) == cudaSuccess;
        ok = ok && cudaEventCreateWithFlags(&ev_wout, cudaEventDisableTiming) == cudaSuccess;
        if (!ok) { s_te = nullptr; }
    }
};
static HgtStreams g_hs;

// ---------------- host orchestration ----------------
extern "C" void kernel_launch(void* const* d_in, const int* in_sizes, int n_in,
                              void* d_out, int out_size)
{
    const int*   inputs      = (const int*)  d_in[0];
    const float* text_hidden = (const float*)d_in[1];
    const float* label_feat  = (const float*)d_in[2];
    const int*   amask       = (const int*)  d_in[3];
    const float* Wt   = (const float*)d_in[4];
    const float* bt   = (const float*)d_in[5];
    const float* Wl   = (const float*)d_in[6];
    const float* bl   = (const float*)d_in[7];
    const float* WK   = (const float*)d_in[8];
    const float* WQ   = (const float*)d_in[9];
    const float* WV   = (const float*)d_in[10];
    const float* PA   = (const float*)d_in[11];
    const float* PM   = (const float*)d_in[12];
    const float* WA   = (const float*)d_in[13];
    const float* Wout = (const float*)d_in[14];
    const float* bout = (const float*)d_in[15];
    float* out = (float*)d_out;

    float *te, *le, *Kb, *paq, *pmv, *mm, *aw, *part, *wqe, *wve;
    __nv_bfloat16 *featb, *woutb;
    cudaGetSymbolAddress((void**)&te,    g_text_enc);
    cudaGetSymbolAddress((void**)&le,    g_le);
    cudaGetSymbolAddress((void**)&Kb,    g_Kb);
    cudaGetSymbolAddress((void**)&paq,   g_PAQ);
    cudaGetSymbolAddress((void**)&pmv,   g_PMV);
    cudaGetSymbolAddress((void**)&mm,    g_M);
    cudaGetSymbolAddress((void**)&aw,    g_aw);
    cudaGetSymbolAddress((void**)&part,  g_part);
    cudaGetSymbolAddress((void**)&wqe,   g_WQe);
    cudaGetSymbolAddress((void**)&wve,   g_WVe);
    cudaGetSymbolAddress((void**)&featb, g_feat_bf);
    cudaGetSymbolAddress((void**)&woutb, g_Wout_bf);

    cudaFuncSetAttribute(attn_fused, cudaFuncAttributeMaxDynamicSharedMemorySize, ATTN_SMEM);

    const bool ovl = (g_hs.s_te != nullptr);
    cudaStream_t ste = ovl ? g_hs.s_te : (cudaStream_t)0;
    cudaStream_t stw = ovl ? g_hs.s_w  : (cudaStream_t)0;

    // ---- fork ----
    if (ovl) {
        cudaEventRecord(g_hs.ev_fork, 0);
        cudaStreamWaitEvent(g_hs.s_te, g_hs.ev_fork, 0);
        cudaStreamWaitEvent(g_hs.s_w,  g_hs.ev_fork, 0);
    }

    // Wout -> bf16 (BW-bound, hidden under compute-bound front)
    wout_to_bf16<<<1024, 256, 0, stw>>>(Wout, woutb, (long)LLAB * KOUT);
    if (ovl) cudaEventRecord(g_hs.ev_wout, g_hs.s_w);

    // text_enc = tanh(text_hidden @ Wt^T + bt)   [16384, 256] K=768  (side)
    tgemm_g<128, 128, 16, 64, 32, 1, false><<<dim3(cdiv(HIDC, 128), cdiv(BBAT * SSEQ, 128), 1), 256, 0, ste>>>(
        text_hidden, Wt, bt, te,
        BBAT * SSEQ, HIDC, DBERT, DBERT, DBERT, HIDC, 0, 0, 0);
    if (ovl) cudaEventRecord(g_hs.ev_te, g_hs.s_te);

    // ---- label-side chain on main stream ----
    prep_eff<<<dim3(24, 2), 256>>>(WQ, WV, PA, PM, wqe, wve);

    tgemm_g<128, 128, 16, 64, 32, 0, false><<<dim3(cdiv(HIDC, 128), cdiv(LLAB, 128), 1), 256>>>(
        label_feat, Wl, bl, le,
        LLAB, HIDC, DBERT, DBERT, DBERT, HIDC, 0, 0, 0);

    for (int layer = 0; layer < 2; layer++) {
        proj_fused<<<dim3(cdiv(HIDC, 64), cdiv(NN3, 64), 9), 128>>>(
            le, WK, wqe, wve, Kb, paq, pmv);

        attn_fused<<<dim3(cdiv(LLAB, 32), NHEAD), 256, ATTN_SMEM>>>(
            paq, Kb, pmv, amask, mm);

        wa_fused<<<dim3(cdiv(HIDC, 64), cdiv(NN3, 64), 3), 128>>>(mm, WA, le);
    }
    if (ovl) cudaEventRecord(g_hs.ev_le, 0);     // le final

    // ---- two label-half pooling chains ----
    if (ovl) cudaStreamWaitEvent(0, g_hs.ev_te, 0);          // chain0 needs te
    if (ovl) cudaStreamWaitEvent(g_hs.s_te, g_hs.ev_le, 0);  // chain1 needs le

    const int L0 = LSPLIT, L1 = LLAB - LSPLIT;   // 300 / 300

    // ---- chain0 on main stream (labels [0, 300)) ----
    tgemm_g<128, 128, 16, 64, 32, 0, false><<<dim3(cdiv(SSEQ, 128), cdiv(L0, 128), BBAT), 256>>>(
        le, te, nullptr, aw,
        L0, SSEQ, HIDC, HIDC, HIDC, SSEQ,
        0, (long)SSEQ * HIDC, (long)LLAB * SSEQ);
    pool_softmax<<<dim3(L0, BBAT), 256>>>(aw, inputs, 0);
    tgemm_g<128, 128, 16, 64, 32, 0, true, true><<<dim3(cdiv(HIDC, 128), cdiv(L0, 128), BBAT), 256>>>(
        aw, te, nullptr, (float*)featb,
        L0, HIDC, SSEQ, SSEQ, HIDC, HIDC,
        (long)LLAB * SSEQ, (long)SSEQ * HIDC, (long)LLAB * HIDC);
    if (ovl) cudaStreamWaitEvent(0, g_hs.ev_wout, 0);
    bgemm_final<<<dim3(cdiv(LLAB, 128), 1, ZSPLIT), 256>>>(featb, woutb, part, 0);

    // ---- chain1 on side stream (labels [300, 600)) ----
    if (ovl) {
        tgemm_g<128, 128, 16, 64, 32, 0, false><<<dim3(cdiv(SSEQ, 128), cdiv(L1, 128), BBAT), 256, 0, ste>>>(
            le + (long)LSPLIT * HIDC, te, nullptr, aw + (long)LSPLIT * SSEQ,
            L1, SSEQ, HIDC, HIDC, HIDC, SSEQ,
            0, (long)SSEQ * HIDC, (long)LLAB * SSEQ);
        pool_softmax<<<dim3(L1, BBAT), 256, 0, ste>>>(aw, inputs, LSPLIT);
        tgemm_g<128, 128, 16, 64, 32, 0, true, true><<<dim3(cdiv(HIDC, 128), cdiv(L1, 128), BBAT), 256, 0, ste>>>(
            aw + (long)LSPLIT * SSEQ, te, nullptr, (float*)(featb + (long)LSPLIT * HIDC),
            L1, HIDC, SSEQ, SSEQ, HIDC, HIDC,
            (long)LLAB * SSEQ, (long)SSEQ * HIDC, (long)LLAB * HIDC);
        cudaStreamWaitEvent(g_hs.s_te, g_hs.ev_wout, 0);
        bgemm_final<<<dim3(cdiv(LLAB, 128), 1, NSPLIT - ZSPLIT), 256, 0, ste>>>(
            featb, woutb, part, ZSPLIT);
        cudaEventRecord(g_hs.ev_c1, g_hs.s_te);
        cudaStreamWaitEvent(0, g_hs.ev_c1, 0);
    } else {
        tgemm_g<128, 128, 16, 64, 32, 0, false><<<dim3(cdiv(SSEQ, 128), cdiv(L1, 128), BBAT), 256>>>(
            le + (long)LSPLIT * HIDC, te, nullptr, aw + (long)LSPLIT * SSEQ,
            L1, SSEQ, HIDC, HIDC, HIDC, SSEQ,
            0, (long)SSEQ * HIDC, (long)LLAB * SSEQ);
        pool_softmax<<<dim3(L1, BBAT), 256>>>(aw, inputs, LSPLIT);
        tgemm_g<128, 128, 16, 64, 32, 0, true, true><<<dim3(cdiv(HIDC, 128), cdiv(L1, 128), BBAT), 256>>>(
            aw + (long)LSPLIT * SSEQ, te, nullptr, (float*)(featb + (long)LSPLIT * HIDC),
            L1, HIDC, SSEQ, SSEQ, HIDC, HIDC,
            (long)LLAB * SSEQ, (long)SSEQ * HIDC, (long)LLAB * HIDC);
        bgemm_final<<<dim3(cdiv(LLAB, 128), 1, NSPLIT - ZSPLIT), 256>>>(
            featb, woutb, part, ZSPLIT);
    }

    final_reduce<<<cdiv(BBAT * LLAB, 256), 256>>>(part, bout, out);
}